// round 2
// baseline (speedup 1.0000x reference)
#include <cuda_runtime.h>
#include <cstddef>

#define B_ 4
#define S_ 2048
#define H_ 256
#define NHEAD_ 4
#define DH_ 64
#define FFN_ 1024
#define M_ (B_ * S_)   // 8192

// ---------------- scratch (no allocation allowed) ----------------
__device__ float g_h  [M_ * H_];
__device__ float g_z  [M_ * H_];
__device__ float g_qkv[M_ * 3 * H_];
__device__ float g_att[M_ * H_];
__device__ float g_ffn[M_ * FFN_];

// ---------------- GEMM: C[M,N] = A[M,K] @ W[N,K]^T (+epilogue) ----------------
// MODE 0: +bias, 1: +bias, relu, 2: +bias +residual, 3: 16*v + sinusoidal PE
template<int MODE>
__global__ void __launch_bounds__(256)
gemm_kernel(const float* __restrict__ A, const float* __restrict__ W,
            const float* __restrict__ bias, const float* __restrict__ res,
            float* __restrict__ C, int M, int N, int K)
{
    const int TM = 128, TN = 64, TK = 16;
    __shared__ float As[TK][TM + 4];
    __shared__ float Bs[TK][TN + 4];

    int tid = threadIdx.x;
    int bm = blockIdx.y * TM;
    int bn = blockIdx.x * TN;
    int row_t = tid >> 4;      // 0..15 -> 8 rows each
    int col_t = tid & 15;      // 0..15 -> 4 cols each

    float acc[8][4];
#pragma unroll
    for (int i = 0; i < 8; i++)
#pragma unroll
        for (int j = 0; j < 4; j++) acc[i][j] = 0.f;

    int am = tid >> 1;            // 0..127
    int ak = (tid & 1) * 8;       // 0 / 8
    int wn = tid >> 2;            // 0..63
    int wk = (tid & 3) * 4;       // 0,4,8,12

    for (int k0 = 0; k0 < K; k0 += TK) {
        const float* Ap = A + (size_t)(bm + am) * K + k0 + ak;
#pragma unroll
        for (int i = 0; i < 8; i++) As[ak + i][am] = Ap[i];
        const float* Wp = W + (size_t)(bn + wn) * K + k0 + wk;
#pragma unroll
        for (int i = 0; i < 4; i++) Bs[wk + i][wn] = Wp[i];
        __syncthreads();

#pragma unroll
        for (int kk = 0; kk < TK; kk++) {
            float a[8], b[4];
#pragma unroll
            for (int i = 0; i < 8; i++) a[i] = As[kk][row_t * 8 + i];
#pragma unroll
            for (int j = 0; j < 4; j++) b[j] = Bs[kk][col_t * 4 + j];
#pragma unroll
            for (int i = 0; i < 8; i++)
#pragma unroll
                for (int j = 0; j < 4; j++) acc[i][j] += a[i] * b[j];
        }
        __syncthreads();
    }

#pragma unroll
    for (int i = 0; i < 8; i++) {
        int m = bm + row_t * 8 + i;
#pragma unroll
        for (int j = 0; j < 4; j++) {
            int n = bn + col_t * 4 + j;
            float v = acc[i][j];
            if (MODE == 3) {
                int s = m & (S_ - 1);
                int pair = n >> 1;
                float freq = expf((float)(2 * pair) * (-9.210340371976184f / 256.0f));
                float ang = (float)s * freq;
                v = 16.f * v + ((n & 1) ? cosf(ang) : sinf(ang));
            } else {
                v += bias[n];
                if (MODE == 1) v = fmaxf(v, 0.f);
                if (MODE == 2) v += res[(size_t)m * N + n];
            }
            C[(size_t)m * N + n] = v;
        }
    }
}

// ---------------- LayerNorm: one warp per 256-wide row ----------------
__global__ void __launch_bounds__(256)
ln_kernel(const float* __restrict__ x, const float* __restrict__ g,
          const float* __restrict__ b, float* __restrict__ y)
{
    int warp = threadIdx.x >> 5;
    int lane = threadIdx.x & 31;
    int row = blockIdx.x * 8 + warp;
    const float* xr = x + (size_t)row * 256;
    float v[8];
    float s = 0.f;
#pragma unroll
    for (int i = 0; i < 8; i++) { v[i] = xr[lane + 32 * i]; s += v[i]; }
#pragma unroll
    for (int o = 16; o; o >>= 1) s += __shfl_xor_sync(~0u, s, o);
    float mu = s * (1.f / 256.f);
    float sq = 0.f;
#pragma unroll
    for (int i = 0; i < 8; i++) { float d = v[i] - mu; sq += d * d; }
#pragma unroll
    for (int o = 16; o; o >>= 1) sq += __shfl_xor_sync(~0u, sq, o);
    float rs = rsqrtf(sq * (1.f / 256.f) + 1e-5f);
    float* yr = y + (size_t)row * 256;
#pragma unroll
    for (int i = 0; i < 8; i++) {
        int c = lane + 32 * i;
        yr[c] = (v[i] - mu) * rs * g[c] + b[c];
    }
}

// ---------------- Banded attention (window |j-i|<=32), warp-per-query ----------------
// grid: (S/8, NHEAD, B), block 256
__global__ void __launch_bounds__(256)
attn_kernel(const float* __restrict__ qkv, float* __restrict__ out)
{
    __shared__ float Qs[8][64];
    __shared__ float Ks[72][65];
    __shared__ float Vs[72][65];
    __shared__ float P[8][72];

    int q0 = blockIdx.x * 8;
    int h = blockIdx.y;
    int bb = blockIdx.z;
    int tid = threadIdx.x;
    const float* base = qkv + (size_t)bb * S_ * (3 * H_);
    int kb = q0 - 32;

    for (int e = tid; e < 8 * 64; e += 256) {
        int r = e >> 6, d = e & 63;
        Qs[r][d] = base[(size_t)(q0 + r) * (3 * H_) + h * 64 + d];
    }
    for (int e = tid; e < 72 * 64; e += 256) {
        int r = e >> 6, d = e & 63;
        int j = kb + r;
        float kk = 0.f, vv = 0.f;
        if (j >= 0 && j < S_) {
            const float* p = base + (size_t)j * (3 * H_) + h * 64 + d;
            kk = p[H_];
            vv = p[2 * H_];
        }
        Ks[r][d] = kk;
        Vs[r][d] = vv;
    }
    __syncthreads();

    int w = tid >> 5, l = tid & 31;
    int qi = q0 + w;
    float sc[3];
#pragma unroll
    for (int t = 0; t < 3; t++) sc[t] = -1e30f;
    int njj = (l < 8) ? 3 : 2;
    for (int t = 0; t < njj; t++) {
        int jj = l + t * 32;
        int j = kb + jj;
        bool ok = (jj >= w) && (jj <= w + 64) && (j >= 0) && (j < S_);
        if (ok) {
            float s = 0.f;
#pragma unroll
            for (int d = 0; d < 64; d++) s += Qs[w][d] * Ks[jj][d];
            sc[t] = s * 0.125f;   // 1/sqrt(64)
        }
    }
    float mx = fmaxf(sc[0], fmaxf(sc[1], sc[2]));
#pragma unroll
    for (int o = 16; o; o >>= 1) mx = fmaxf(mx, __shfl_xor_sync(~0u, mx, o));
    float pv[3];
    float ssum = 0.f;
#pragma unroll
    for (int t = 0; t < 3; t++) {
        pv[t] = (sc[t] > -1e29f) ? expf(sc[t] - mx) : 0.f;
        ssum += pv[t];
    }
#pragma unroll
    for (int o = 16; o; o >>= 1) ssum += __shfl_xor_sync(~0u, ssum, o);
    float inv = 1.f / ssum;
    for (int t = 0; t < njj; t++) P[w][l + t * 32] = pv[t] * inv;
    __syncwarp();

    float o0 = 0.f, o1 = 0.f;
#pragma unroll 8
    for (int jj = 0; jj < 72; jj++) {
        float p = P[w][jj];
        o0 += p * Vs[jj][l];
        o1 += p * Vs[jj][l + 32];
    }
    float* op = out + ((size_t)(bb * S_ + qi)) * H_ + h * 64;
    op[l] = o0;
    op[l + 32] = o1;
}

// ---------------- host orchestration ----------------
static void run_gemm(int mode, const float* A, const float* W, const float* bias,
                     const float* res, float* C, int M, int N, int K)
{
    dim3 grid(N / 64, M / 128);
    switch (mode) {
        case 0: gemm_kernel<0><<<grid, 256>>>(A, W, bias, res, C, M, N, K); break;
        case 1: gemm_kernel<1><<<grid, 256>>>(A, W, bias, res, C, M, N, K); break;
        case 2: gemm_kernel<2><<<grid, 256>>>(A, W, bias, res, C, M, N, K); break;
        case 3: gemm_kernel<3><<<grid, 256>>>(A, W, bias, res, C, M, N, K); break;
    }
}

extern "C" void kernel_launch(void* const* d_in, const int* in_sizes, int n_in,
                              void* d_out, int out_size)
{
    const float* x     = (const float*)d_in[0];
    const float* w_in  = (const float*)d_in[1];
    const float* w_out = (const float*)d_in[2];
    const float* b_out = (const float*)d_in[3];
    const float* qkv_w = (const float*)d_in[4];
    const float* qkv_b = (const float*)d_in[5];
    const float* out_w = (const float*)d_in[6];
    const float* out_b = (const float*)d_in[7];
    const float* ln1_g = (const float*)d_in[8];
    const float* ln1_b = (const float*)d_in[9];
    const float* ln2_g = (const float*)d_in[10];
    const float* ln2_b = (const float*)d_in[11];
    const float* ff1_w = (const float*)d_in[12];
    const float* ff1_b = (const float*)d_in[13];
    const float* ff2_w = (const float*)d_in[14];
    const float* ff2_b = (const float*)d_in[15];
    const float* lnf_g = (const float*)d_in[16];
    const float* lnf_b = (const float*)d_in[17];
    float* out = (float*)d_out;

    float *h, *z, *qkv, *att, *ffn;
    cudaGetSymbolAddress((void**)&h,   g_h);
    cudaGetSymbolAddress((void**)&z,   g_z);
    cudaGetSymbolAddress((void**)&qkv, g_qkv);
    cudaGetSymbolAddress((void**)&att, g_att);
    cudaGetSymbolAddress((void**)&ffn, g_ffn);

    // embed: h = 16 * x @ w_in^T + PE
    run_gemm(3, x, w_in, nullptr, nullptr, h, M_, H_, H_);

    for (int l = 0; l < 3; l++) {
        // ln1
        ln_kernel<<<M_ / 8, 256>>>(h, ln1_g + l * H_, ln1_b + l * H_, z);
        // qkv
        run_gemm(0, z, qkv_w + (size_t)l * 3 * H_ * H_, qkv_b + l * 3 * H_, nullptr,
                 qkv, M_, 3 * H_, H_);
        // attention
        attn_kernel<<<dim3(S_ / 8, NHEAD_, B_), 256>>>(qkv, att);
        // out proj + residual
        run_gemm(2, att, out_w + (size_t)l * H_ * H_, out_b + l * H_, h, h, M_, H_, H_);
        // ln2
        ln_kernel<<<M_ / 8, 256>>>(h, ln2_g + l * H_, ln2_b + l * H_, z);
        // ff1 + relu
        run_gemm(1, z, ff1_w + (size_t)l * FFN_ * H_, ff1_b + l * FFN_, nullptr,
                 ffn, M_, FFN_, H_);
        // ff2 + residual
        run_gemm(2, ffn, ff2_w + (size_t)l * H_ * FFN_, ff2_b + l * H_, h, h, M_, H_, FFN_);
    }

    // final ln + out proj
    ln_kernel<<<M_ / 8, 256>>>(h, lnf_g, lnf_b, z);
    run_gemm(0, z, w_out, b_out, nullptr, out, M_, H_, H_);
}

// round 3
// speedup vs baseline: 1.7972x; 1.7972x over previous
#include <cuda_runtime.h>
#include <cstdint>
#include <cstddef>

#define B_ 4
#define S_ 2048
#define H_ 256
#define NHEAD_ 4
#define DH_ 64
#define FFN_ 1024
#define M_ (B_ * S_)   // 8192

// ---------------- scratch (no allocation allowed) ----------------
__device__ float g_h  [M_ * H_];
__device__ float g_z  [M_ * H_];
__device__ float g_qkv[M_ * 3 * H_];
__device__ float g_att[M_ * H_];
__device__ float g_ffn[M_ * FFN_];

__device__ __forceinline__ uint32_t f2tf32(float f) {
    uint32_t u;
    asm("cvt.rna.tf32.f32 %0, %1;" : "=r"(u) : "f"(f));
    return u;
}

// ---------------- TF32 tensor-core GEMM ----------------
// C[M,N] = A[M,K] @ W[N,K]^T (+epilogue)
// MODE 0: +bias, 1: +bias+relu, 2: +bias+residual, 3: 16*v + sinusoidal PE
// Block: 256 threads (8 warps), tile 128(M) x 64(N), TK=32.
// Warp grid: 4(M) x 2(N), each warp 32x32 via 2x4 m16n8k8 tf32 mma.
template<int MODE>
__global__ void __launch_bounds__(256)
gemm_tc(const float* __restrict__ A, const float* __restrict__ W,
        const float* __restrict__ bias, const float* __restrict__ res,
        float* __restrict__ C, int M, int N, int K)
{
    // stride 136 / 72: stride mod 32 == 8 -> fragment gather is bank-conflict-free
    __shared__ uint32_t As[32][136];
    __shared__ uint32_t Bs[32][72];

    const int tid = threadIdx.x;
    const int lane = tid & 31;
    const int wid = tid >> 5;
    const int bm = blockIdx.y * 128;
    const int bn = blockIdx.x * 64;
    const int warp_m = (wid & 3) * 32;
    const int warp_n = (wid >> 2) * 32;
    const int gid = lane >> 2;   // 0..7
    const int tig = lane & 3;    // 0..3

    float acc[2][4][4];
#pragma unroll
    for (int i = 0; i < 2; i++)
#pragma unroll
        for (int j = 0; j < 4; j++)
#pragma unroll
            for (int c = 0; c < 4; c++) acc[i][j][c] = 0.f;

    for (int k0 = 0; k0 < K; k0 += 32) {
        // stage A: 128 rows x 32 k = 1024 float4, 256 thr -> 4 each
#pragma unroll
        for (int p = 0; p < 4; p++) {
            int e = tid + p * 256;
            int r = e >> 3, c = e & 7;
            float4 v = *(const float4*)(A + (size_t)(bm + r) * K + k0 + c * 4);
            As[c * 4 + 0][r] = f2tf32(v.x);
            As[c * 4 + 1][r] = f2tf32(v.y);
            As[c * 4 + 2][r] = f2tf32(v.z);
            As[c * 4 + 3][r] = f2tf32(v.w);
        }
        // stage W: 64 rows x 32 k = 512 float4, 256 thr -> 2 each
#pragma unroll
        for (int p = 0; p < 2; p++) {
            int e = tid + p * 256;
            int r = e >> 3, c = e & 7;
            float4 v = *(const float4*)(W + (size_t)(bn + r) * K + k0 + c * 4);
            Bs[c * 4 + 0][r] = f2tf32(v.x);
            Bs[c * 4 + 1][r] = f2tf32(v.y);
            Bs[c * 4 + 2][r] = f2tf32(v.z);
            Bs[c * 4 + 3][r] = f2tf32(v.w);
        }
        __syncthreads();

#pragma unroll
        for (int ks = 0; ks < 32; ks += 8) {
            uint32_t a[2][4], b[4][2];
#pragma unroll
            for (int mt = 0; mt < 2; mt++) {
                int m0 = warp_m + mt * 16 + gid;
                a[mt][0] = As[ks + tig][m0];
                a[mt][1] = As[ks + tig][m0 + 8];
                a[mt][2] = As[ks + tig + 4][m0];
                a[mt][3] = As[ks + tig + 4][m0 + 8];
            }
#pragma unroll
            for (int nt = 0; nt < 4; nt++) {
                int n0 = warp_n + nt * 8 + gid;
                b[nt][0] = Bs[ks + tig][n0];
                b[nt][1] = Bs[ks + tig + 4][n0];
            }
#pragma unroll
            for (int mt = 0; mt < 2; mt++)
#pragma unroll
                for (int nt = 0; nt < 4; nt++) {
                    asm volatile(
                        "mma.sync.aligned.m16n8k8.row.col.f32.tf32.tf32.f32 "
                        "{%0,%1,%2,%3}, {%4,%5,%6,%7}, {%8,%9}, {%0,%1,%2,%3};\n"
                        : "+f"(acc[mt][nt][0]), "+f"(acc[mt][nt][1]),
                          "+f"(acc[mt][nt][2]), "+f"(acc[mt][nt][3])
                        : "r"(a[mt][0]), "r"(a[mt][1]), "r"(a[mt][2]), "r"(a[mt][3]),
                          "r"(b[nt][0]), "r"(b[nt][1]));
                }
        }
        __syncthreads();
    }

    // epilogue: c0,c1 -> (row gid, cols 2*tig, 2*tig+1); c2,c3 -> row gid+8
#pragma unroll
    for (int mt = 0; mt < 2; mt++) {
#pragma unroll
        for (int half = 0; half < 2; half++) {
            int m = bm + warp_m + mt * 16 + gid + half * 8;
#pragma unroll
            for (int nt = 0; nt < 4; nt++) {
                int n = bn + warp_n + nt * 8 + 2 * tig;
                float v0 = acc[mt][nt][half * 2 + 0];
                float v1 = acc[mt][nt][half * 2 + 1];
                if (MODE == 3) {
                    int s = m & (S_ - 1);
                    float f0 = expf((float)(n & ~1) * (-9.210340371976184f / 256.0f));
                    // n is even here; n+1 is odd (cos of same pair)
                    float ang = (float)s * f0;
                    v0 = 16.f * v0 + sinf(ang);
                    v1 = 16.f * v1 + cosf(ang);
                } else {
                    v0 += bias[n];
                    v1 += bias[n + 1];
                    if (MODE == 1) { v0 = fmaxf(v0, 0.f); v1 = fmaxf(v1, 0.f); }
                    if (MODE == 2) {
                        const float* rp = res + (size_t)m * N + n;
                        v0 += rp[0];
                        v1 += rp[1];
                    }
                }
                *(float2*)(C + (size_t)m * N + n) = make_float2(v0, v1);
            }
        }
    }
}

// ---------------- LayerNorm: one warp per 256-wide row ----------------
__global__ void __launch_bounds__(256)
ln_kernel(const float* __restrict__ x, const float* __restrict__ g,
          const float* __restrict__ b, float* __restrict__ y)
{
    int warp = threadIdx.x >> 5;
    int lane = threadIdx.x & 31;
    int row = blockIdx.x * 8 + warp;
    const float* xr = x + (size_t)row * 256;
    float v[8];
    float s = 0.f;
#pragma unroll
    for (int i = 0; i < 8; i++) { v[i] = xr[lane + 32 * i]; s += v[i]; }
#pragma unroll
    for (int o = 16; o; o >>= 1) s += __shfl_xor_sync(~0u, s, o);
    float mu = s * (1.f / 256.f);
    float sq = 0.f;
#pragma unroll
    for (int i = 0; i < 8; i++) { float d = v[i] - mu; sq += d * d; }
#pragma unroll
    for (int o = 16; o; o >>= 1) sq += __shfl_xor_sync(~0u, sq, o);
    float rs = rsqrtf(sq * (1.f / 256.f) + 1e-5f);
    float* yr = y + (size_t)row * 256;
#pragma unroll
    for (int i = 0; i < 8; i++) {
        int c = lane + 32 * i;
        yr[c] = (v[i] - mu) * rs * g[c] + b[c];
    }
}

// ---------------- Banded attention (window |j-i|<=32), warp-per-query ----------------
// grid: (S/8, NHEAD, B), block 256
__global__ void __launch_bounds__(256)
attn_kernel(const float* __restrict__ qkv, float* __restrict__ out)
{
    __shared__ float Qs[8][64];
    __shared__ float Ks[72][65];
    __shared__ float Vs[72][65];
    __shared__ float P[8][72];

    int q0 = blockIdx.x * 8;
    int h = blockIdx.y;
    int bb = blockIdx.z;
    int tid = threadIdx.x;
    const float* base = qkv + (size_t)bb * S_ * (3 * H_);
    int kb = q0 - 32;

    for (int e = tid; e < 8 * 64; e += 256) {
        int r = e >> 6, d = e & 63;
        Qs[r][d] = base[(size_t)(q0 + r) * (3 * H_) + h * 64 + d];
    }
    for (int e = tid; e < 72 * 64; e += 256) {
        int r = e >> 6, d = e & 63;
        int j = kb + r;
        float kk = 0.f, vv = 0.f;
        if (j >= 0 && j < S_) {
            const float* p = base + (size_t)j * (3 * H_) + h * 64 + d;
            kk = p[H_];
            vv = p[2 * H_];
        }
        Ks[r][d] = kk;
        Vs[r][d] = vv;
    }
    __syncthreads();

    int w = tid >> 5, l = tid & 31;
    int qi = q0 + w;
    float sc[3];
#pragma unroll
    for (int t = 0; t < 3; t++) sc[t] = -1e30f;
    int njj = (l < 8) ? 3 : 2;
    for (int t = 0; t < njj; t++) {
        int jj = l + t * 32;
        int j = kb + jj;
        bool ok = (jj >= w) && (jj <= w + 64) && (j >= 0) && (j < S_);
        if (ok) {
            float s = 0.f;
#pragma unroll
            for (int d = 0; d < 64; d++) s += Qs[w][d] * Ks[jj][d];
            sc[t] = s * 0.125f;   // 1/sqrt(64)
        }
    }
    float mx = fmaxf(sc[0], fmaxf(sc[1], sc[2]));
#pragma unroll
    for (int o = 16; o; o >>= 1) mx = fmaxf(mx, __shfl_xor_sync(~0u, mx, o));
    float pv[3];
    float ssum = 0.f;
#pragma unroll
    for (int t = 0; t < 3; t++) {
        pv[t] = (sc[t] > -1e29f) ? expf(sc[t] - mx) : 0.f;
        ssum += pv[t];
    }
#pragma unroll
    for (int o = 16; o; o >>= 1) ssum += __shfl_xor_sync(~0u, ssum, o);
    float inv = 1.f / ssum;
    for (int t = 0; t < njj; t++) P[w][l + t * 32] = pv[t] * inv;
    __syncwarp();

    float o0 = 0.f, o1 = 0.f;
#pragma unroll 8
    for (int jj = 0; jj < 72; jj++) {
        float p = P[w][jj];
        o0 += p * Vs[jj][l];
        o1 += p * Vs[jj][l + 32];
    }
    float* op = out + ((size_t)(bb * S_ + qi)) * H_ + h * 64;
    op[l] = o0;
    op[l + 32] = o1;
}

// ---------------- host orchestration ----------------
static void run_gemm(int mode, const float* A, const float* W, const float* bias,
                     const float* res, float* C, int M, int N, int K)
{
    dim3 grid(N / 64, M / 128);
    switch (mode) {
        case 0: gemm_tc<0><<<grid, 256>>>(A, W, bias, res, C, M, N, K); break;
        case 1: gemm_tc<1><<<grid, 256>>>(A, W, bias, res, C, M, N, K); break;
        case 2: gemm_tc<2><<<grid, 256>>>(A, W, bias, res, C, M, N, K); break;
        case 3: gemm_tc<3><<<grid, 256>>>(A, W, bias, res, C, M, N, K); break;
    }
}

extern "C" void kernel_launch(void* const* d_in, const int* in_sizes, int n_in,
                              void* d_out, int out_size)
{
    const float* x     = (const float*)d_in[0];
    const float* w_in  = (const float*)d_in[1];
    const float* w_out = (const float*)d_in[2];
    const float* b_out = (const float*)d_in[3];
    const float* qkv_w = (const float*)d_in[4];
    const float* qkv_b = (const float*)d_in[5];
    const float* out_w = (const float*)d_in[6];
    const float* out_b = (const float*)d_in[7];
    const float* ln1_g = (const float*)d_in[8];
    const float* ln1_b = (const float*)d_in[9];
    const float* ln2_g = (const float*)d_in[10];
    const float* ln2_b = (const float*)d_in[11];
    const float* ff1_w = (const float*)d_in[12];
    const float* ff1_b = (const float*)d_in[13];
    const float* ff2_w = (const float*)d_in[14];
    const float* ff2_b = (const float*)d_in[15];
    const float* lnf_g = (const float*)d_in[16];
    const float* lnf_b = (const float*)d_in[17];
    float* out = (float*)d_out;

    float *h, *z, *qkv, *att, *ffn;
    cudaGetSymbolAddress((void**)&h,   g_h);
    cudaGetSymbolAddress((void**)&z,   g_z);
    cudaGetSymbolAddress((void**)&qkv, g_qkv);
    cudaGetSymbolAddress((void**)&att, g_att);
    cudaGetSymbolAddress((void**)&ffn, g_ffn);

    // embed: h = 16 * x @ w_in^T + PE
    run_gemm(3, x, w_in, nullptr, nullptr, h, M_, H_, H_);

    for (int l = 0; l < 3; l++) {
        ln_kernel<<<M_ / 8, 256>>>(h, ln1_g + l * H_, ln1_b + l * H_, z);
        run_gemm(0, z, qkv_w + (size_t)l * 3 * H_ * H_, qkv_b + l * 3 * H_, nullptr,
                 qkv, M_, 3 * H_, H_);
        attn_kernel<<<dim3(S_ / 8, NHEAD_, B_), 256>>>(qkv, att);
        run_gemm(2, att, out_w + (size_t)l * H_ * H_, out_b + l * H_, h, h, M_, H_, H_);
        ln_kernel<<<M_ / 8, 256>>>(h, ln2_g + l * H_, ln2_b + l * H_, z);
        run_gemm(1, z, ff1_w + (size_t)l * FFN_ * H_, ff1_b + l * FFN_, nullptr,
                 ffn, M_, FFN_, H_);
        run_gemm(2, ffn, ff2_w + (size_t)l * H_ * FFN_, ff2_b + l * H_, h, h, M_, H_, FFN_);
    }

    ln_kernel<<<M_ / 8, 256>>>(h, lnf_g, lnf_b, z);
    run_gemm(0, z, w_out, b_out, nullptr, out, M_, H_, H_);
}

// round 4
// speedup vs baseline: 3.0068x; 1.6731x over previous
#include <cuda_runtime.h>
#include <cstdint>
#include <cstddef>

#define B_ 4
#define S_ 2048
#define H_ 256
#define NHEAD_ 4
#define DH_ 64
#define FFN_ 1024
#define M_ (B_ * S_)   // 8192

// ---------------- scratch (no allocation allowed) ----------------
__device__ float g_h  [M_ * H_];
__device__ float g_z  [M_ * H_];
__device__ float g_qkv[M_ * 3 * H_];
__device__ float g_att[M_ * H_];
__device__ float g_ffn[M_ * FFN_];

__device__ __forceinline__ uint32_t f2tf32(float f) {
    uint32_t u;
    asm("cvt.rna.tf32.f32 %0, %1;" : "=r"(u) : "f"(f));
    return u;
}

__device__ __forceinline__ void cp_async16(uint32_t smem, const void* gmem) {
    asm volatile("cp.async.cg.shared.global [%0], [%1], 16;\n" :: "r"(smem), "l"(gmem));
}
__device__ __forceinline__ void cp_commit() {
    asm volatile("cp.async.commit_group;\n");
}
template<int N>
__device__ __forceinline__ void cp_wait() {
    asm volatile("cp.async.wait_group %0;\n" :: "n"(N));
}

// ---------------- TF32 tensor-core GEMM, 2-stage cp.async pipeline ----------------
// C[M,N] = A[M,K] @ W[N,K]^T (+epilogue)
// MODE 0: +bias, 1: +bias+relu, 2: +bias+residual, 3: 16*v + sinusoidal PE
// Block 256 thr (8 warps), tile 128(M) x 64(N), TK=32. Warp: 32x32 (2x4 m16n8k8).
template<int MODE>
__global__ void __launch_bounds__(256)
gemm_tc(const float* __restrict__ A, const float* __restrict__ W,
        const float* __restrict__ bias, const float* __restrict__ res,
        float* __restrict__ C, int M, int N, int K)
{
    // stride 36 floats: fragment gather (4*gid + tig) hits all 32 banks
    __shared__ float As[2][128][36];
    __shared__ float Bs[2][64][36];

    const int tid = threadIdx.x;
    const int lane = tid & 31;
    const int wid = tid >> 5;
    const int bm = blockIdx.y * 128;
    const int bn = blockIdx.x * 64;
    const int warp_m = (wid & 3) * 32;
    const int warp_n = (wid >> 2) * 32;
    const int gid = lane >> 2;   // 0..7
    const int tig = lane & 3;    // 0..3

    const int ar = tid >> 1;            // 0..127  (A: 2 chunks per thread pass? see below)
    // A tile: 128 rows x 8 float4-chunks = 1024 transfers, 4 per thread
    // B tile: 64 rows x 8 chunks = 512 transfers, 2 per thread

    float acc[2][4][4];
#pragma unroll
    for (int i = 0; i < 2; i++)
#pragma unroll
        for (int j = 0; j < 4; j++)
#pragma unroll
            for (int c = 0; c < 4; c++) acc[i][j][c] = 0.f;

    const int nk = K >> 5;

    // stage function inlined via macro-style lambda
    auto stage = [&](int buf, int k0) {
#pragma unroll
        for (int p = 0; p < 4; p++) {
            int e = tid + p * 256;
            int r = e >> 3, c = e & 7;
            uint32_t s = (uint32_t)__cvta_generic_to_shared(&As[buf][r][c * 4]);
            cp_async16(s, A + (size_t)(bm + r) * K + k0 + c * 4);
        }
#pragma unroll
        for (int p = 0; p < 2; p++) {
            int e = tid + p * 256;
            int r = e >> 3, c = e & 7;
            uint32_t s = (uint32_t)__cvta_generic_to_shared(&Bs[buf][r][c * 4]);
            cp_async16(s, W + (size_t)(bn + r) * K + k0 + c * 4);
        }
        cp_commit();
    };

    stage(0, 0);

    for (int it = 0; it < nk; it++) {
        if (it + 1 < nk) {
            stage((it + 1) & 1, (it + 1) * 32);
            cp_wait<1>();
        } else {
            cp_wait<0>();
        }
        __syncthreads();

        const float (*Asb)[36] = As[it & 1];
        const float (*Bsb)[36] = Bs[it & 1];

#pragma unroll
        for (int ks = 0; ks < 32; ks += 8) {
            uint32_t a[2][4], b[4][2];
#pragma unroll
            for (int mt = 0; mt < 2; mt++) {
                int m0 = warp_m + mt * 16 + gid;
                a[mt][0] = f2tf32(Asb[m0][ks + tig]);
                a[mt][1] = f2tf32(Asb[m0 + 8][ks + tig]);
                a[mt][2] = f2tf32(Asb[m0][ks + tig + 4]);
                a[mt][3] = f2tf32(Asb[m0 + 8][ks + tig + 4]);
            }
#pragma unroll
            for (int nt = 0; nt < 4; nt++) {
                int n0 = warp_n + nt * 8 + gid;
                b[nt][0] = f2tf32(Bsb[n0][ks + tig]);
                b[nt][1] = f2tf32(Bsb[n0][ks + tig + 4]);
            }
#pragma unroll
            for (int mt = 0; mt < 2; mt++)
#pragma unroll
                for (int nt = 0; nt < 4; nt++) {
                    asm volatile(
                        "mma.sync.aligned.m16n8k8.row.col.f32.tf32.tf32.f32 "
                        "{%0,%1,%2,%3}, {%4,%5,%6,%7}, {%8,%9}, {%0,%1,%2,%3};\n"
                        : "+f"(acc[mt][nt][0]), "+f"(acc[mt][nt][1]),
                          "+f"(acc[mt][nt][2]), "+f"(acc[mt][nt][3])
                        : "r"(a[mt][0]), "r"(a[mt][1]), "r"(a[mt][2]), "r"(a[mt][3]),
                          "r"(b[nt][0]), "r"(b[nt][1]));
                }
        }
        __syncthreads();
    }

    // epilogue: c0,c1 -> (row gid, cols 2*tig, 2*tig+1); c2,c3 -> row gid+8
#pragma unroll
    for (int mt = 0; mt < 2; mt++) {
#pragma unroll
        for (int half = 0; half < 2; half++) {
            int m = bm + warp_m + mt * 16 + gid + half * 8;
#pragma unroll
            for (int nt = 0; nt < 4; nt++) {
                int n = bn + warp_n + nt * 8 + 2 * tig;
                float v0 = acc[mt][nt][half * 2 + 0];
                float v1 = acc[mt][nt][half * 2 + 1];
                if (MODE == 3) {
                    int s = m & (S_ - 1);
                    float f0 = expf((float)(n & ~1) * (-9.210340371976184f / 256.0f));
                    float ang = (float)s * f0;
                    v0 = 16.f * v0 + sinf(ang);
                    v1 = 16.f * v1 + cosf(ang);
                } else {
                    v0 += bias[n];
                    v1 += bias[n + 1];
                    if (MODE == 1) { v0 = fmaxf(v0, 0.f); v1 = fmaxf(v1, 0.f); }
                    if (MODE == 2) {
                        const float* rp = res + (size_t)m * N + n;
                        v0 += rp[0];
                        v1 += rp[1];
                    }
                }
                *(float2*)(C + (size_t)m * N + n) = make_float2(v0, v1);
            }
        }
    }
}

// ---------------- LayerNorm: one warp per 256-wide row ----------------
__global__ void __launch_bounds__(256)
ln_kernel(const float* __restrict__ x, const float* __restrict__ g,
          const float* __restrict__ b, float* __restrict__ y)
{
    int warp = threadIdx.x >> 5;
    int lane = threadIdx.x & 31;
    int row = blockIdx.x * 8 + warp;
    const float* xr = x + (size_t)row * 256;
    float v[8];
    float s = 0.f;
#pragma unroll
    for (int i = 0; i < 8; i++) { v[i] = xr[lane + 32 * i]; s += v[i]; }
#pragma unroll
    for (int o = 16; o; o >>= 1) s += __shfl_xor_sync(~0u, s, o);
    float mu = s * (1.f / 256.f);
    float sq = 0.f;
#pragma unroll
    for (int i = 0; i < 8; i++) { float d = v[i] - mu; sq += d * d; }
#pragma unroll
    for (int o = 16; o; o >>= 1) sq += __shfl_xor_sync(~0u, sq, o);
    float rs = rsqrtf(sq * (1.f / 256.f) + 1e-5f);
    float* yr = y + (size_t)row * 256;
#pragma unroll
    for (int i = 0; i < 8; i++) {
        int c = lane + 32 * i;
        yr[c] = (v[i] - mu) * rs * g[c] + b[c];
    }
}

// ---------------- Banded attention (window |j-i|<=32), warp-per-query ----------------
// grid: (S/8, NHEAD, B), block 256. Rows padded to 68 floats (17 float4):
// K/V float4 reads: word offset 4*jj mod 32 spans all banks per 8-lane phase.
__global__ void __launch_bounds__(256)
attn_kernel(const float* __restrict__ qkv, float* __restrict__ out)
{
    __shared__ float4 Qs[8][17];
    __shared__ float4 Ks[72][17];
    __shared__ float4 Vs[72][17];
    __shared__ float P[8][72];

    int q0 = blockIdx.x * 8;
    int h = blockIdx.y;
    int bb = blockIdx.z;
    int tid = threadIdx.x;
    const float* base = qkv + (size_t)bb * S_ * (3 * H_);
    int kb = q0 - 32;

    // stage Q: 8 rows x 16 float4
    if (tid < 128) {
        int r = tid >> 4, d4 = tid & 15;
        Qs[r][d4] = *(const float4*)(base + (size_t)(q0 + r) * (3 * H_) + h * 64 + d4 * 4);
    }
    // stage K, V: 72 rows x 16 float4 each
    for (int e = tid; e < 72 * 16; e += 256) {
        int r = e >> 4, d4 = e & 15;
        int j = kb + r;
        float4 kk = make_float4(0.f, 0.f, 0.f, 0.f);
        float4 vv = kk;
        if (j >= 0 && j < S_) {
            const float* p = base + (size_t)j * (3 * H_) + h * 64 + d4 * 4;
            kk = *(const float4*)(p + H_);
            vv = *(const float4*)(p + 2 * H_);
        }
        Ks[r][d4] = kk;
        Vs[r][d4] = vv;
    }
    __syncthreads();

    int w = tid >> 5, l = tid & 31;
    int qi = q0 + w;
    float sc[3];
#pragma unroll
    for (int t = 0; t < 3; t++) sc[t] = -1e30f;
    int njj = (l < 8) ? 3 : 2;
    for (int t = 0; t < njj; t++) {
        int jj = l + t * 32;
        int j = kb + jj;
        bool ok = (jj >= w) && (jj <= w + 64) && (j >= 0) && (j < S_);
        if (ok) {
            float s = 0.f;
#pragma unroll
            for (int d4 = 0; d4 < 16; d4++) {
                float4 q = Qs[w][d4];
                float4 k = Ks[jj][d4];
                s += q.x * k.x + q.y * k.y + q.z * k.z + q.w * k.w;
            }
            sc[t] = s * 0.125f;   // 1/sqrt(64)
        }
    }
    float mx = fmaxf(sc[0], fmaxf(sc[1], sc[2]));
#pragma unroll
    for (int o = 16; o; o >>= 1) mx = fmaxf(mx, __shfl_xor_sync(~0u, mx, o));
    float pv[3];
    float ssum = 0.f;
#pragma unroll
    for (int t = 0; t < 3; t++) {
        pv[t] = (sc[t] > -1e29f) ? expf(sc[t] - mx) : 0.f;
        ssum += pv[t];
    }
#pragma unroll
    for (int o = 16; o; o >>= 1) ssum += __shfl_xor_sync(~0u, ssum, o);
    float inv = 1.f / ssum;
    for (int t = 0; t < njj; t++) P[w][l + t * 32] = pv[t] * inv;
    __syncwarp();

    // PV: lane covers d = 2l, 2l+1 (float2)
    float ox = 0.f, oy = 0.f;
#pragma unroll 8
    for (int jj = 0; jj < 72; jj++) {
        float p = P[w][jj];
        float2 v = ((const float2*)&Vs[jj][0])[l];
        ox += p * v.x;
        oy += p * v.y;
    }
    float* op = out + ((size_t)(bb * S_ + qi)) * H_ + h * 64;
    ((float2*)op)[l] = make_float2(ox, oy);
}

// ---------------- host orchestration ----------------
static void run_gemm(int mode, const float* A, const float* W, const float* bias,
                     const float* res, float* C, int M, int N, int K)
{
    dim3 grid(N / 64, M / 128);
    switch (mode) {
        case 0: gemm_tc<0><<<grid, 256>>>(A, W, bias, res, C, M, N, K); break;
        case 1: gemm_tc<1><<<grid, 256>>>(A, W, bias, res, C, M, N, K); break;
        case 2: gemm_tc<2><<<grid, 256>>>(A, W, bias, res, C, M, N, K); break;
        case 3: gemm_tc<3><<<grid, 256>>>(A, W, bias, res, C, M, N, K); break;
    }
}

extern "C" void kernel_launch(void* const* d_in, const int* in_sizes, int n_in,
                              void* d_out, int out_size)
{
    const float* x     = (const float*)d_in[0];
    const float* w_in  = (const float*)d_in[1];
    const float* w_out = (const float*)d_in[2];
    const float* b_out = (const float*)d_in[3];
    const float* qkv_w = (const float*)d_in[4];
    const float* qkv_b = (const float*)d_in[5];
    const float* out_w = (const float*)d_in[6];
    const float* out_b = (const float*)d_in[7];
    const float* ln1_g = (const float*)d_in[8];
    const float* ln1_b = (const float*)d_in[9];
    const float* ln2_g = (const float*)d_in[10];
    const float* ln2_b = (const float*)d_in[11];
    const float* ff1_w = (const float*)d_in[12];
    const float* ff1_b = (const float*)d_in[13];
    const float* ff2_w = (const float*)d_in[14];
    const float* ff2_b = (const float*)d_in[15];
    const float* lnf_g = (const float*)d_in[16];
    const float* lnf_b = (const float*)d_in[17];
    float* out = (float*)d_out;

    float *h, *z, *qkv, *att, *ffn;
    cudaGetSymbolAddress((void**)&h,   g_h);
    cudaGetSymbolAddress((void**)&z,   g_z);
    cudaGetSymbolAddress((void**)&qkv, g_qkv);
    cudaGetSymbolAddress((void**)&att, g_att);
    cudaGetSymbolAddress((void**)&ffn, g_ffn);

    // embed: h = 16 * x @ w_in^T + PE
    run_gemm(3, x, w_in, nullptr, nullptr, h, M_, H_, H_);

    for (int l = 0; l < 3; l++) {
        ln_kernel<<<M_ / 8, 256>>>(h, ln1_g + l * H_, ln1_b + l * H_, z);
        run_gemm(0, z, qkv_w + (size_t)l * 3 * H_ * H_, qkv_b + l * 3 * H_, nullptr,
                 qkv, M_, 3 * H_, H_);
        attn_kernel<<<dim3(S_ / 8, NHEAD_, B_), 256>>>(qkv, att);
        run_gemm(2, att, out_w + (size_t)l * H_ * H_, out_b + l * H_, h, h, M_, H_, H_);
        ln_kernel<<<M_ / 8, 256>>>(h, ln2_g + l * H_, ln2_b + l * H_, z);
        run_gemm(1, z, ff1_w + (size_t)l * FFN_ * H_, ff1_b + l * FFN_, nullptr,
                 ffn, M_, FFN_, H_);
        run_gemm(2, ffn, ff2_w + (size_t)l * H_ * FFN_, ff2_b + l * H_, h, h, M_, H_, FFN_);
    }

    ln_kernel<<<M_ / 8, 256>>>(h, lnf_g, lnf_b, z);
    run_gemm(0, z, w_out, b_out, nullptr, out, M_, H_, H_);
}

// round 8
// speedup vs baseline: 3.5861x; 1.1927x over previous
#include <cuda_runtime.h>
#include <cstdint>
#include <cstddef>

#define B_ 4
#define S_ 2048
#define H_ 256
#define NHEAD_ 4
#define DH_ 64
#define FFN_ 1024
#define M_ (B_ * S_)   // 8192

// ---------------- scratch (no allocation allowed) ----------------
__device__ float g_h  [M_ * H_];
__device__ float g_z  [M_ * H_];
__device__ float g_qkv[M_ * 3 * H_];
__device__ float g_att[M_ * H_];
__device__ float g_ffn[M_ * FFN_];

__device__ __forceinline__ uint32_t f2tf32(float f) {
    uint32_t u;
    asm("cvt.rna.tf32.f32 %0, %1;" : "=r"(u) : "f"(f));
    return u;
}

__device__ __forceinline__ void cp_async16(uint32_t smem, const void* gmem) {
    asm volatile("cp.async.cg.shared.global [%0], [%1], 16;\n" :: "r"(smem), "l"(gmem));
}
__device__ __forceinline__ void cp_commit() {
    asm volatile("cp.async.commit_group;\n");
}
template<int N>
__device__ __forceinline__ void cp_wait() {
    asm volatile("cp.async.wait_group %0;\n" :: "n"(N));
}

#define MMA_TF32(acc, a, b0, b1)                                              \
    asm volatile(                                                             \
        "mma.sync.aligned.m16n8k8.row.col.f32.tf32.tf32.f32 "                 \
        "{%0,%1,%2,%3}, {%4,%5,%6,%7}, {%8,%9}, {%0,%1,%2,%3};\n"             \
        : "+f"(acc[0]), "+f"(acc[1]), "+f"(acc[2]), "+f"(acc[3])              \
        : "r"(a[0]), "r"(a[1]), "r"(a[2]), "r"(a[3]), "r"(b0), "r"(b1))

// ---------------- TF32 tensor-core GEMM, 2-stage cp.async pipeline ----------------
// C[M,N] = A[M,K] @ W[N,K]^T (+epilogue)
// MODE 0: +bias, 1: +bias+relu, 2: +bias+residual, 3: 16*v + sinusoidal PE
template<int MODE>
__global__ void __launch_bounds__(256)
gemm_tc(const float* __restrict__ A, const float* __restrict__ W,
        const float* __restrict__ bias, const float* __restrict__ res,
        float* __restrict__ C, int M, int N, int K)
{
    __shared__ float As[2][128][36];
    __shared__ float Bs[2][64][36];

    const int tid = threadIdx.x;
    const int lane = tid & 31;
    const int wid = tid >> 5;
    const int bm = blockIdx.y * 128;
    const int bn = blockIdx.x * 64;
    const int warp_m = (wid & 3) * 32;
    const int warp_n = (wid >> 2) * 32;
    const int gid = lane >> 2;
    const int tig = lane & 3;

    float acc[2][4][4];
#pragma unroll
    for (int i = 0; i < 2; i++)
#pragma unroll
        for (int j = 0; j < 4; j++)
#pragma unroll
            for (int c = 0; c < 4; c++) acc[i][j][c] = 0.f;

    const int nk = K >> 5;

    auto stage = [&](int buf, int k0) {
#pragma unroll
        for (int p = 0; p < 4; p++) {
            int e = tid + p * 256;
            int r = e >> 3, c = e & 7;
            uint32_t s = (uint32_t)__cvta_generic_to_shared(&As[buf][r][c * 4]);
            cp_async16(s, A + (size_t)(bm + r) * K + k0 + c * 4);
        }
#pragma unroll
        for (int p = 0; p < 2; p++) {
            int e = tid + p * 256;
            int r = e >> 3, c = e & 7;
            uint32_t s = (uint32_t)__cvta_generic_to_shared(&Bs[buf][r][c * 4]);
            cp_async16(s, W + (size_t)(bn + r) * K + k0 + c * 4);
        }
        cp_commit();
    };

    stage(0, 0);

    for (int it = 0; it < nk; it++) {
        if (it + 1 < nk) {
            stage((it + 1) & 1, (it + 1) * 32);
            cp_wait<1>();
        } else {
            cp_wait<0>();
        }
        __syncthreads();

        const float (*Asb)[36] = As[it & 1];
        const float (*Bsb)[36] = Bs[it & 1];

#pragma unroll
        for (int ks = 0; ks < 32; ks += 8) {
            uint32_t a[2][4], b[4][2];
#pragma unroll
            for (int mt = 0; mt < 2; mt++) {
                int m0 = warp_m + mt * 16 + gid;
                a[mt][0] = f2tf32(Asb[m0][ks + tig]);
                a[mt][1] = f2tf32(Asb[m0 + 8][ks + tig]);
                a[mt][2] = f2tf32(Asb[m0][ks + tig + 4]);
                a[mt][3] = f2tf32(Asb[m0 + 8][ks + tig + 4]);
            }
#pragma unroll
            for (int nt = 0; nt < 4; nt++) {
                int n0 = warp_n + nt * 8 + gid;
                b[nt][0] = f2tf32(Bsb[n0][ks + tig]);
                b[nt][1] = f2tf32(Bsb[n0][ks + tig + 4]);
            }
#pragma unroll
            for (int mt = 0; mt < 2; mt++)
#pragma unroll
                for (int nt = 0; nt < 4; nt++)
                    MMA_TF32(acc[mt][nt], a[mt], b[nt][0], b[nt][1]);
        }
        __syncthreads();
    }

#pragma unroll
    for (int mt = 0; mt < 2; mt++) {
#pragma unroll
        for (int half = 0; half < 2; half++) {
            int m = bm + warp_m + mt * 16 + gid + half * 8;
#pragma unroll
            for (int nt = 0; nt < 4; nt++) {
                int n = bn + warp_n + nt * 8 + 2 * tig;
                float v0 = acc[mt][nt][half * 2 + 0];
                float v1 = acc[mt][nt][half * 2 + 1];
                if (MODE == 3) {
                    int s = m & (S_ - 1);
                    float f0 = expf((float)(n & ~1) * (-9.210340371976184f / 256.0f));
                    float ang = (float)s * f0;
                    v0 = 16.f * v0 + sinf(ang);
                    v1 = 16.f * v1 + cosf(ang);
                } else {
                    v0 += bias[n];
                    v1 += bias[n + 1];
                    if (MODE == 1) { v0 = fmaxf(v0, 0.f); v1 = fmaxf(v1, 0.f); }
                    if (MODE == 2) {
                        const float* rp = res + (size_t)m * N + n;
                        v0 += rp[0];
                        v1 += rp[1];
                    }
                }
                *(float2*)(C + (size_t)m * N + n) = make_float2(v0, v1);
            }
        }
    }
}

// ---------------- LayerNorm: warp per row, float4 ----------------
__global__ void __launch_bounds__(256)
ln_kernel(const float* __restrict__ x, const float* __restrict__ g,
          const float* __restrict__ b, float* __restrict__ y)
{
    int warp = threadIdx.x >> 5;
    int lane = threadIdx.x & 31;
    int row = blockIdx.x * 8 + warp;
    const float4* xr = (const float4*)(x + (size_t)row * 256);
    float4 v0 = xr[lane], v1 = xr[lane + 32];
    float s = v0.x + v0.y + v0.z + v0.w + v1.x + v1.y + v1.z + v1.w;
#pragma unroll
    for (int o = 16; o; o >>= 1) s += __shfl_xor_sync(~0u, s, o);
    float mu = s * (1.f / 256.f);
    float sq = 0.f;
    sq += (v0.x - mu) * (v0.x - mu) + (v0.y - mu) * (v0.y - mu)
        + (v0.z - mu) * (v0.z - mu) + (v0.w - mu) * (v0.w - mu);
    sq += (v1.x - mu) * (v1.x - mu) + (v1.y - mu) * (v1.y - mu)
        + (v1.z - mu) * (v1.z - mu) + (v1.w - mu) * (v1.w - mu);
#pragma unroll
    for (int o = 16; o; o >>= 1) sq += __shfl_xor_sync(~0u, sq, o);
    float rs = rsqrtf(sq * (1.f / 256.f) + 1e-5f);
    float4 g0 = ((const float4*)g)[lane], g1 = ((const float4*)g)[lane + 32];
    float4 b0 = ((const float4*)b)[lane], b1 = ((const float4*)b)[lane + 32];
    float4 o0, o1;
    o0.x = (v0.x - mu) * rs * g0.x + b0.x;
    o0.y = (v0.y - mu) * rs * g0.y + b0.y;
    o0.z = (v0.z - mu) * rs * g0.z + b0.z;
    o0.w = (v0.w - mu) * rs * g0.w + b0.w;
    o1.x = (v1.x - mu) * rs * g1.x + b1.x;
    o1.y = (v1.y - mu) * rs * g1.y + b1.y;
    o1.z = (v1.z - mu) * rs * g1.z + b1.z;
    o1.w = (v1.w - mu) * rs * g1.w + b1.w;
    float4* yr = (float4*)(y + (size_t)row * 256);
    yr[lane] = o0;
    yr[lane + 32] = o1;
}

// ---------------- Tensor-core banded attention ----------------
// Block: (batch, head, 64-query tile). Key window = 128 rows [q0-32, q0+95].
// Pass1: S = Q @ K^T (64x128) via tf32 mma -> mask -> Ps (smem)
// Softmax: warp-per-row, 1/sum deferred to PV epilogue
// Pass2: O = P @ V via tf32 mma (V read untransposed as B fragment)
#define BQ 64
#define KW 128
#define QSTR 68
#define KSTR 68
#define PSTR 132
#define ATT_SMEM_FLOATS (64 * QSTR + 128 * KSTR + 128 * KSTR + 64 * PSTR + 64)

extern __shared__ float att_smem[];

__global__ void __launch_bounds__(256)
attn_mma(const float* __restrict__ qkv, float* __restrict__ out)
{
    float* Qs   = att_smem;                 // 64 x 68
    float* Ks   = Qs + 64 * QSTR;           // 128 x 68
    float* Vs   = Ks + 128 * KSTR;          // 128 x 68
    float* Ps   = Vs + 128 * KSTR;          // 64 x 132
    float* Rinv = Ps + 64 * PSTR;           // 64

    const int q0 = blockIdx.x * BQ;
    const int h = blockIdx.y;
    const int bb = blockIdx.z;
    const int tid = threadIdx.x;
    const int lane = tid & 31;
    const int wid = tid >> 5;
    const int gid = lane >> 2;
    const int tig = lane & 3;
    const float* base = qkv + (size_t)bb * S_ * (3 * H_) + h * 64;
    const int kb = q0 - 32;

    // stage Q (64 x 64)
#pragma unroll
    for (int p = 0; p < 4; p++) {
        int e = tid + p * 256;
        int r = e >> 4, d4 = e & 15;
        *(float4*)&Qs[r * QSTR + d4 * 4] =
            *(const float4*)(base + (size_t)(q0 + r) * (3 * H_) + d4 * 4);
    }
    // stage K, V (128 x 64 each, zero-padded out of range)
#pragma unroll
    for (int p = 0; p < 8; p++) {
        int e = tid + p * 256;
        int r = e >> 4, d4 = e & 15;
        int j = kb + r;
        float4 kk = make_float4(0.f, 0.f, 0.f, 0.f);
        float4 vv = kk;
        if (j >= 0 && j < S_) {
            const float* pp = base + (size_t)j * (3 * H_) + d4 * 4;
            kk = *(const float4*)(pp + H_);
            vv = *(const float4*)(pp + 2 * H_);
        }
        *(float4*)&Ks[r * KSTR + d4 * 4] = kk;
        *(float4*)&Vs[r * KSTR + d4 * 4] = vv;
    }
    __syncthreads();

    const int warp_m = (wid & 3) * 16;

    // ---- Pass 1: scores 64x128, warp grid 4m x 2n (warp tile 16x64) ----
    {
        const int warp_n = (wid >> 2) * 64;
        float acc[8][4];
#pragma unroll
        for (int j = 0; j < 8; j++)
#pragma unroll
            for (int c = 0; c < 4; c++) acc[j][c] = 0.f;

#pragma unroll
        for (int ks = 0; ks < 64; ks += 8) {
            uint32_t a[4];
            a[0] = f2tf32(Qs[(warp_m + gid) * QSTR + ks + tig]);
            a[1] = f2tf32(Qs[(warp_m + gid + 8) * QSTR + ks + tig]);
            a[2] = f2tf32(Qs[(warp_m + gid) * QSTR + ks + tig + 4]);
            a[3] = f2tf32(Qs[(warp_m + gid + 8) * QSTR + ks + tig + 4]);
#pragma unroll
            for (int nt = 0; nt < 8; nt++) {
                int n0 = warp_n + nt * 8 + gid;
                uint32_t b0 = f2tf32(Ks[n0 * KSTR + ks + tig]);
                uint32_t b1 = f2tf32(Ks[n0 * KSTR + ks + tig + 4]);
                MMA_TF32(acc[nt], a, b0, b1);
            }
        }

        // mask + store to Ps
#pragma unroll
        for (int nt = 0; nt < 8; nt++) {
#pragma unroll
            for (int half = 0; half < 2; half++) {
                int r = warp_m + gid + half * 8;
                int c = warp_n + nt * 8 + 2 * tig;
                float v0 = acc[nt][half * 2 + 0];
                float v1 = acc[nt][half * 2 + 1];
                int j0 = kb + c, j1 = j0 + 1;
                bool ok0 = (c >= r) && (c <= r + 64) && (j0 >= 0) && (j0 < S_);
                bool ok1 = (c + 1 >= r) && (c + 1 <= r + 64) && (j1 >= 0) && (j1 < S_);
                v0 = ok0 ? v0 * 0.125f : -1e30f;
                v1 = ok1 ? v1 * 0.125f : -1e30f;
                *(float2*)&Ps[r * PSTR + c] = make_float2(v0, v1);
            }
        }
    }
    __syncthreads();

    // ---- Softmax: warp per row (8 rows/warp), 4 cols/lane ----
    {
#pragma unroll
        for (int i = 0; i < 8; i++) {
            int r = wid * 8 + i;
            float4 v = *(float4*)&Ps[r * PSTR + lane * 4];
            float mx = fmaxf(fmaxf(v.x, v.y), fmaxf(v.z, v.w));
#pragma unroll
            for (int o = 16; o; o >>= 1) mx = fmaxf(mx, __shfl_xor_sync(~0u, mx, o));
            v.x = __expf(v.x - mx);
            v.y = __expf(v.y - mx);
            v.z = __expf(v.z - mx);
            v.w = __expf(v.w - mx);
            float s = v.x + v.y + v.z + v.w;
#pragma unroll
            for (int o = 16; o; o >>= 1) s += __shfl_xor_sync(~0u, s, o);
            *(float4*)&Ps[r * PSTR + lane * 4] = v;
            if (lane == 0) Rinv[r] = 1.f / s;
        }
    }
    __syncthreads();

    // ---- Pass 2: O = P @ V (64x64), warp grid 4m x 2n (warp tile 16x32) ----
    {
        const int warp_n = (wid >> 2) * 32;
        float acc[4][4];
#pragma unroll
        for (int j = 0; j < 4; j++)
#pragma unroll
            for (int c = 0; c < 4; c++) acc[j][c] = 0.f;

#pragma unroll
        for (int k0 = 0; k0 < 128; k0 += 8) {
            uint32_t a[4];
            a[0] = f2tf32(Ps[(warp_m + gid) * PSTR + k0 + tig]);
            a[1] = f2tf32(Ps[(warp_m + gid + 8) * PSTR + k0 + tig]);
            a[2] = f2tf32(Ps[(warp_m + gid) * PSTR + k0 + tig + 4]);
            a[3] = f2tf32(Ps[(warp_m + gid + 8) * PSTR + k0 + tig + 4]);
#pragma unroll
            for (int nt = 0; nt < 4; nt++) {
                int d0 = warp_n + nt * 8 + gid;
                uint32_t b0 = f2tf32(Vs[(k0 + tig) * KSTR + d0]);
                uint32_t b1 = f2tf32(Vs[(k0 + tig + 4) * KSTR + d0]);
                MMA_TF32(acc[nt], a, b0, b1);
            }
        }

#pragma unroll
        for (int nt = 0; nt < 4; nt++) {
#pragma unroll
            for (int half = 0; half < 2; half++) {
                int r = warp_m + gid + half * 8;
                float sc = Rinv[r];
                int c = warp_n + nt * 8 + 2 * tig;
                float2 o = make_float2(acc[nt][half * 2] * sc,
                                       acc[nt][half * 2 + 1] * sc);
                *(float2*)(out + (size_t)(bb * S_ + q0 + r) * H_ + h * 64 + c) = o;
            }
        }
    }
}

// ---------------- host orchestration ----------------
static void run_gemm(int mode, const float* A, const float* W, const float* bias,
                     const float* res, float* C, int M, int N, int K)
{
    dim3 grid(N / 64, M / 128);
    switch (mode) {
        case 0: gemm_tc<0><<<grid, 256>>>(A, W, bias, res, C, M, N, K); break;
        case 1: gemm_tc<1><<<grid, 256>>>(A, W, bias, res, C, M, N, K); break;
        case 2: gemm_tc<2><<<grid, 256>>>(A, W, bias, res, C, M, N, K); break;
        case 3: gemm_tc<3><<<grid, 256>>>(A, W, bias, res, C, M, N, K); break;
    }
}

extern "C" void kernel_launch(void* const* d_in, const int* in_sizes, int n_in,
                              void* d_out, int out_size)
{
    const float* x     = (const float*)d_in[0];
    const float* w_in  = (const float*)d_in[1];
    const float* w_out = (const float*)d_in[2];
    const float* b_out = (const float*)d_in[3];
    const float* qkv_w = (const float*)d_in[4];
    const float* qkv_b = (const float*)d_in[5];
    const float* out_w = (const float*)d_in[6];
    const float* out_b = (const float*)d_in[7];
    const float* ln1_g = (const float*)d_in[8];
    const float* ln1_b = (const float*)d_in[9];
    const float* ln2_g = (const float*)d_in[10];
    const float* ln2_b = (const float*)d_in[11];
    const float* ff1_w = (const float*)d_in[12];
    const float* ff1_b = (const float*)d_in[13];
    const float* ff2_w = (const float*)d_in[14];
    const float* ff2_b = (const float*)d_in[15];
    const float* lnf_g = (const float*)d_in[16];
    const float* lnf_b = (const float*)d_in[17];
    float* out = (float*)d_out;

    float *h, *z, *qkv, *att, *ffn;
    cudaGetSymbolAddress((void**)&h,   g_h);
    cudaGetSymbolAddress((void**)&z,   g_z);
    cudaGetSymbolAddress((void**)&qkv, g_qkv);
    cudaGetSymbolAddress((void**)&att, g_att);
    cudaGetSymbolAddress((void**)&ffn, g_ffn);

    const int att_smem_bytes = ATT_SMEM_FLOATS * 4;
    cudaFuncSetAttribute(attn_mma, cudaFuncAttributeMaxDynamicSharedMemorySize,
                         att_smem_bytes);

    // embed: h = 16 * x @ w_in^T + PE
    run_gemm(3, x, w_in, nullptr, nullptr, h, M_, H_, H_);

    for (int l = 0; l < 3; l++) {
        ln_kernel<<<M_ / 8, 256>>>(h, ln1_g + l * H_, ln1_b + l * H_, z);
        run_gemm(0, z, qkv_w + (size_t)l * 3 * H_ * H_, qkv_b + l * 3 * H_, nullptr,
                 qkv, M_, 3 * H_, H_);
        attn_mma<<<dim3(S_ / BQ, NHEAD_, B_), 256, att_smem_bytes>>>(qkv, att);
        run_gemm(2, att, out_w + (size_t)l * H_ * H_, out_b + l * H_, h, h, M_, H_, H_);
        ln_kernel<<<M_ / 8, 256>>>(h, ln2_g + l * H_, ln2_b + l * H_, z);
        run_gemm(1, z, ff1_w + (size_t)l * FFN_ * H_, ff1_b + l * FFN_, nullptr,
                 ffn, M_, FFN_, H_);
        run_gemm(2, ffn, ff2_w + (size_t)l * H_ * FFN_, ff2_b + l * H_, h, h, M_, H_, FFN_);
    }

    ln_kernel<<<M_ / 8, 256>>>(h, lnf_g, lnf_b, z);
    run_gemm(0, z, w_out, b_out, nullptr, out, M_, H_, H_);
}

// round 9
// speedup vs baseline: 3.6734x; 1.0243x over previous
#include <cuda_runtime.h>
#include <cstdint>
#include <cstddef>

#define B_ 4
#define S_ 2048
#define H_ 256
#define NHEAD_ 4
#define DH_ 64
#define FFN_ 1024
#define M_ (B_ * S_)   // 8192

// weight-scratch segment offsets (floats)
#define O_WIN   0
#define O_WOUT  65536
#define O_QKV   131072
#define O_OUTW  720896
#define O_FF1   917504
#define O_FF2   1703936
#define WTOT    2490368
#define XTOT    2097152
#define TOT     (WTOT + XTOT)

// ---------------- scratch (no allocation allowed) ----------------
__device__ float g_h  [M_ * H_];
__device__ float g_z  [M_ * H_];
__device__ float g_qkv[M_ * 3 * H_];
__device__ float g_att[M_ * H_];
__device__ float g_ffn[M_ * FFN_];
__device__ float g_wc [WTOT];
__device__ float g_xr [XTOT];

__device__ __forceinline__ uint32_t f2tf32(float f) {
    uint32_t u;
    asm("cvt.rna.tf32.f32 %0, %1;" : "=r"(u) : "f"(f));
    return u;
}
__device__ __forceinline__ float rnd32(float f) { return __uint_as_float(f2tf32(f)); }
__device__ __forceinline__ uint32_t asu(float f) { return __float_as_uint(f); }

__device__ __forceinline__ void cp_async16(uint32_t smem, const void* gmem) {
    asm volatile("cp.async.cg.shared.global [%0], [%1], 16;\n" :: "r"(smem), "l"(gmem));
}
__device__ __forceinline__ void cp_commit() {
    asm volatile("cp.async.commit_group;\n");
}
template<int N>
__device__ __forceinline__ void cp_wait() {
    asm volatile("cp.async.wait_group %0;\n" :: "n"(N));
}

#define MMA_TF32(acc, a, b0, b1)                                              \
    asm volatile(                                                             \
        "mma.sync.aligned.m16n8k8.row.col.f32.tf32.tf32.f32 "                 \
        "{%0,%1,%2,%3}, {%4,%5,%6,%7}, {%8,%9}, {%0,%1,%2,%3};\n"             \
        : "+f"(acc[0]), "+f"(acc[1]), "+f"(acc[2]), "+f"(acc[3])              \
        : "r"(a[0]), "r"(a[1]), "r"(a[2]), "r"(a[3]), "r"(b0), "r"(b1))

// ---------------- prep: round weights + x to tf32 once per launch ----------------
__global__ void __launch_bounds__(256)
prep_cvt(const float* __restrict__ w_in, const float* __restrict__ w_out,
         const float* __restrict__ qkv_w, const float* __restrict__ out_w,
         const float* __restrict__ ff1_w, const float* __restrict__ ff2_w,
         const float* __restrict__ x, float* __restrict__ wc, float* __restrict__ xr)
{
    int i = (blockIdx.x * 256 + threadIdx.x) * 4;
    if (i >= TOT) return;
    const float* s;
    float* d;
    if (i < O_QKV) {
        s = (i < O_WOUT) ? (w_in + i) : (w_out + (i - O_WOUT));
        d = wc + i;
    } else if (i < O_OUTW) { s = qkv_w + (i - O_QKV);  d = wc + i; }
    else if (i < O_FF1)    { s = out_w + (i - O_OUTW); d = wc + i; }
    else if (i < O_FF2)    { s = ff1_w + (i - O_FF1);  d = wc + i; }
    else if (i < WTOT)     { s = ff2_w + (i - O_FF2);  d = wc + i; }
    else                   { s = x + (i - WTOT);       d = xr + (i - WTOT); }
    float4 v = *(const float4*)s;
    v.x = rnd32(v.x); v.y = rnd32(v.y); v.z = rnd32(v.z); v.w = rnd32(v.w);
    *(float4*)d = v;
}

// ---------------- TF32 tensor-core GEMM, 128x128 tile, cp.async pipeline ----------------
// Inputs A and W are PRE-ROUNDED to tf32 bit pattern: no cvt in the inner loop.
// MODE 0: +bias, 1: +bias+relu, 2: +bias+residual, 3: 16*v + sinusoidal PE
// RND: round outputs to tf32 (when consumer is a GEMM/attention operand)
#define GEMM_SMEM_BYTES (4 * 128 * 36 * 4 * 2)   // As+Bs, 2 stages: 73728

template<int MODE, bool RND>
__global__ void __launch_bounds__(256)
gemm_tc(const float* __restrict__ A, const float* __restrict__ W,
        const float* __restrict__ bias, const float* __restrict__ res,
        float* __restrict__ C, int M, int N, int K)
{
    extern __shared__ float gsm[];
    float (*As)[128][36] = (float (*)[128][36])gsm;
    float (*Bs)[128][36] = (float (*)[128][36])(gsm + 2 * 128 * 36);

    const int tid = threadIdx.x;
    const int lane = tid & 31;
    const int wid = tid >> 5;
    const int bm = blockIdx.y * 128;
    const int bn = blockIdx.x * 128;
    const int warp_m = (wid & 3) * 32;
    const int warp_n = (wid >> 2) * 64;
    const int gid = lane >> 2;
    const int tig = lane & 3;

    float acc[2][8][4];
#pragma unroll
    for (int i = 0; i < 2; i++)
#pragma unroll
        for (int j = 0; j < 8; j++)
#pragma unroll
            for (int c = 0; c < 4; c++) acc[i][j][c] = 0.f;

    const int nk = K >> 5;

    auto stage = [&](int buf, int k0) {
#pragma unroll
        for (int p = 0; p < 4; p++) {
            int e = tid + p * 256;
            int r = e >> 3, c = e & 7;
            uint32_t s = (uint32_t)__cvta_generic_to_shared(&As[buf][r][c * 4]);
            cp_async16(s, A + (size_t)(bm + r) * K + k0 + c * 4);
        }
#pragma unroll
        for (int p = 0; p < 4; p++) {
            int e = tid + p * 256;
            int r = e >> 3, c = e & 7;
            uint32_t s = (uint32_t)__cvta_generic_to_shared(&Bs[buf][r][c * 4]);
            cp_async16(s, W + (size_t)(bn + r) * K + k0 + c * 4);
        }
        cp_commit();
    };

    stage(0, 0);

    for (int it = 0; it < nk; it++) {
        if (it + 1 < nk) {
            stage((it + 1) & 1, (it + 1) * 32);
            cp_wait<1>();
        } else {
            cp_wait<0>();
        }
        __syncthreads();

        const float (*Asb)[36] = As[it & 1];
        const float (*Bsb)[36] = Bs[it & 1];

#pragma unroll
        for (int ks = 0; ks < 32; ks += 8) {
            uint32_t a[2][4];
#pragma unroll
            for (int mt = 0; mt < 2; mt++) {
                int m0 = warp_m + mt * 16 + gid;
                a[mt][0] = asu(Asb[m0][ks + tig]);
                a[mt][1] = asu(Asb[m0 + 8][ks + tig]);
                a[mt][2] = asu(Asb[m0][ks + tig + 4]);
                a[mt][3] = asu(Asb[m0 + 8][ks + tig + 4]);
            }
#pragma unroll
            for (int nt = 0; nt < 8; nt++) {
                int n0 = warp_n + nt * 8 + gid;
                uint32_t b0 = asu(Bsb[n0][ks + tig]);
                uint32_t b1 = asu(Bsb[n0][ks + tig + 4]);
#pragma unroll
                for (int mt = 0; mt < 2; mt++)
                    MMA_TF32(acc[mt][nt], a[mt], b0, b1);
            }
        }
        __syncthreads();
    }

#pragma unroll
    for (int mt = 0; mt < 2; mt++) {
#pragma unroll
        for (int half = 0; half < 2; half++) {
            int m = bm + warp_m + mt * 16 + gid + half * 8;
#pragma unroll
            for (int nt = 0; nt < 8; nt++) {
                int n = bn + warp_n + nt * 8 + 2 * tig;
                float v0 = acc[mt][nt][half * 2 + 0];
                float v1 = acc[mt][nt][half * 2 + 1];
                if (MODE == 3) {
                    int s = m & (S_ - 1);
                    float f0 = expf((float)(n & ~1) * (-9.210340371976184f / 256.0f));
                    float ang = (float)s * f0;
                    v0 = 16.f * v0 + sinf(ang);
                    v1 = 16.f * v1 + cosf(ang);
                } else {
                    v0 += bias[n];
                    v1 += bias[n + 1];
                    if (MODE == 1) { v0 = fmaxf(v0, 0.f); v1 = fmaxf(v1, 0.f); }
                    if (MODE == 2) {
                        const float* rp = res + (size_t)m * N + n;
                        v0 += rp[0];
                        v1 += rp[1];
                    }
                }
                if (RND) { v0 = rnd32(v0); v1 = rnd32(v1); }
                *(float2*)(C + (size_t)m * N + n) = make_float2(v0, v1);
            }
        }
    }
}

// ---------------- LayerNorm: warp per row, float4, tf32-rounded output ----------------
__global__ void __launch_bounds__(256)
ln_kernel(const float* __restrict__ x, const float* __restrict__ g,
          const float* __restrict__ b, float* __restrict__ y)
{
    int warp = threadIdx.x >> 5;
    int lane = threadIdx.x & 31;
    int row = blockIdx.x * 8 + warp;
    const float4* xr = (const float4*)(x + (size_t)row * 256);
    float4 v0 = xr[lane], v1 = xr[lane + 32];
    float s = v0.x + v0.y + v0.z + v0.w + v1.x + v1.y + v1.z + v1.w;
#pragma unroll
    for (int o = 16; o; o >>= 1) s += __shfl_xor_sync(~0u, s, o);
    float mu = s * (1.f / 256.f);
    float sq = 0.f;
    sq += (v0.x - mu) * (v0.x - mu) + (v0.y - mu) * (v0.y - mu)
        + (v0.z - mu) * (v0.z - mu) + (v0.w - mu) * (v0.w - mu);
    sq += (v1.x - mu) * (v1.x - mu) + (v1.y - mu) * (v1.y - mu)
        + (v1.z - mu) * (v1.z - mu) + (v1.w - mu) * (v1.w - mu);
#pragma unroll
    for (int o = 16; o; o >>= 1) sq += __shfl_xor_sync(~0u, sq, o);
    float rs = rsqrtf(sq * (1.f / 256.f) + 1e-5f);
    float4 g0 = ((const float4*)g)[lane], g1 = ((const float4*)g)[lane + 32];
    float4 b0 = ((const float4*)b)[lane], b1 = ((const float4*)b)[lane + 32];
    float4 o0, o1;
    o0.x = rnd32((v0.x - mu) * rs * g0.x + b0.x);
    o0.y = rnd32((v0.y - mu) * rs * g0.y + b0.y);
    o0.z = rnd32((v0.z - mu) * rs * g0.z + b0.z);
    o0.w = rnd32((v0.w - mu) * rs * g0.w + b0.w);
    o1.x = rnd32((v1.x - mu) * rs * g1.x + b1.x);
    o1.y = rnd32((v1.y - mu) * rs * g1.y + b1.y);
    o1.z = rnd32((v1.z - mu) * rs * g1.z + b1.z);
    o1.w = rnd32((v1.w - mu) * rs * g1.w + b1.w);
    float4* yr = (float4*)(y + (size_t)row * 256);
    yr[lane] = o0;
    yr[lane + 32] = o1;
}

// ---------------- Tensor-core banded attention (Q/Ps smem union, 2 CTAs/SM) ----------------
#define BQ 64
#define QSTR 68
#define KSTR 68
#define PSTR 132
#define ATT_SMEM_FLOATS (64 * PSTR + 128 * KSTR + 128 * KSTR + 64)

__global__ void __launch_bounds__(256)
attn_mma(const float* __restrict__ qkv, float* __restrict__ out)
{
    extern __shared__ float asmem[];
    float* Ps   = asmem;                  // 64 x 132 (also Qs: 64 x 68 during pass 1)
    float* Qs   = asmem;
    float* Ks   = asmem + 64 * PSTR;      // 128 x 68
    float* Vs   = Ks + 128 * KSTR;        // 128 x 68
    float* Rinv = Vs + 128 * KSTR;        // 64

    const int q0 = blockIdx.x * BQ;
    const int h = blockIdx.y;
    const int bb = blockIdx.z;
    const int tid = threadIdx.x;
    const int lane = tid & 31;
    const int wid = tid >> 5;
    const int gid = lane >> 2;
    const int tig = lane & 3;
    const float* base = qkv + (size_t)bb * S_ * (3 * H_) + h * 64;
    const int kb = q0 - 32;

    // stage Q (64 x 64) into the Ps region with QSTR stride
#pragma unroll
    for (int p = 0; p < 4; p++) {
        int e = tid + p * 256;
        int r = e >> 4, d4 = e & 15;
        *(float4*)&Qs[r * QSTR + d4 * 4] =
            *(const float4*)(base + (size_t)(q0 + r) * (3 * H_) + d4 * 4);
    }
    // stage K, V (128 x 64 each, zero-padded out of range)
#pragma unroll
    for (int p = 0; p < 8; p++) {
        int e = tid + p * 256;
        int r = e >> 4, d4 = e & 15;
        int j = kb + r;
        float4 kk = make_float4(0.f, 0.f, 0.f, 0.f);
        float4 vv = kk;
        if (j >= 0 && j < S_) {
            const float* pp = base + (size_t)j * (3 * H_) + d4 * 4;
            kk = *(const float4*)(pp + H_);
            vv = *(const float4*)(pp + 2 * H_);
        }
        *(float4*)&Ks[r * KSTR + d4 * 4] = kk;
        *(float4*)&Vs[r * KSTR + d4 * 4] = vv;
    }
    __syncthreads();

    const int warp_m = (wid & 3) * 16;

    // ---- Pass 1: scores 64x128, warp grid 4m x 2n (warp tile 16x64) ----
    float sacc[8][4];
    {
        const int warp_n = (wid >> 2) * 64;
#pragma unroll
        for (int j = 0; j < 8; j++)
#pragma unroll
            for (int c = 0; c < 4; c++) sacc[j][c] = 0.f;

#pragma unroll
        for (int ks = 0; ks < 64; ks += 8) {
            uint32_t a[4];
            a[0] = asu(Qs[(warp_m + gid) * QSTR + ks + tig]);
            a[1] = asu(Qs[(warp_m + gid + 8) * QSTR + ks + tig]);
            a[2] = asu(Qs[(warp_m + gid) * QSTR + ks + tig + 4]);
            a[3] = asu(Qs[(warp_m + gid + 8) * QSTR + ks + tig + 4]);
#pragma unroll
            for (int nt = 0; nt < 8; nt++) {
                int n0 = warp_n + nt * 8 + gid;
                uint32_t b0 = asu(Ks[n0 * KSTR + ks + tig]);
                uint32_t b1 = asu(Ks[n0 * KSTR + ks + tig + 4]);
                MMA_TF32(sacc[nt], a, b0, b1);
            }
        }
    }
    __syncthreads();   // all Q reads complete before Ps overwrites the union

    // mask + store scores to Ps
    {
        const int warp_n = (wid >> 2) * 64;
#pragma unroll
        for (int nt = 0; nt < 8; nt++) {
#pragma unroll
            for (int half = 0; half < 2; half++) {
                int r = warp_m + gid + half * 8;
                int c = warp_n + nt * 8 + 2 * tig;
                float v0 = sacc[nt][half * 2 + 0];
                float v1 = sacc[nt][half * 2 + 1];
                int j0 = kb + c, j1 = j0 + 1;
                bool ok0 = (c >= r) && (c <= r + 64) && (j0 >= 0) && (j0 < S_);
                bool ok1 = (c + 1 >= r) && (c + 1 <= r + 64) && (j1 >= 0) && (j1 < S_);
                v0 = ok0 ? v0 * 0.125f : -1e30f;
                v1 = ok1 ? v1 * 0.125f : -1e30f;
                *(float2*)&Ps[r * PSTR + c] = make_float2(v0, v1);
            }
        }
    }
    __syncthreads();

    // ---- Softmax: warp per row (8 rows/warp), 4 cols/lane; round P to tf32 ----
    {
#pragma unroll
        for (int i = 0; i < 8; i++) {
            int r = wid * 8 + i;
            float4 v = *(float4*)&Ps[r * PSTR + lane * 4];
            float mx = fmaxf(fmaxf(v.x, v.y), fmaxf(v.z, v.w));
#pragma unroll
            for (int o = 16; o; o >>= 1) mx = fmaxf(mx, __shfl_xor_sync(~0u, mx, o));
            v.x = __expf(v.x - mx);
            v.y = __expf(v.y - mx);
            v.z = __expf(v.z - mx);
            v.w = __expf(v.w - mx);
            float s = v.x + v.y + v.z + v.w;
#pragma unroll
            for (int o = 16; o; o >>= 1) s += __shfl_xor_sync(~0u, s, o);
            v.x = rnd32(v.x); v.y = rnd32(v.y); v.z = rnd32(v.z); v.w = rnd32(v.w);
            *(float4*)&Ps[r * PSTR + lane * 4] = v;
            if (lane == 0) Rinv[r] = 1.f / s;
        }
    }
    __syncthreads();

    // ---- Pass 2: O = P @ V (64x64), warp grid 4m x 2n (warp tile 16x32) ----
    {
        const int warp_n = (wid >> 2) * 32;
        float acc[4][4];
#pragma unroll
        for (int j = 0; j < 4; j++)
#pragma unroll
            for (int c = 0; c < 4; c++) acc[j][c] = 0.f;

#pragma unroll
        for (int k0 = 0; k0 < 128; k0 += 8) {
            uint32_t a[4];
            a[0] = asu(Ps[(warp_m + gid) * PSTR + k0 + tig]);
            a[1] = asu(Ps[(warp_m + gid + 8) * PSTR + k0 + tig]);
            a[2] = asu(Ps[(warp_m + gid) * PSTR + k0 + tig + 4]);
            a[3] = asu(Ps[(warp_m + gid + 8) * PSTR + k0 + tig + 4]);
#pragma unroll
            for (int nt = 0; nt < 4; nt++) {
                int d0 = warp_n + nt * 8 + gid;
                uint32_t b0 = asu(Vs[(k0 + tig) * KSTR + d0]);
                uint32_t b1 = asu(Vs[(k0 + tig + 4) * KSTR + d0]);
                MMA_TF32(acc[nt], a, b0, b1);
            }
        }

#pragma unroll
        for (int nt = 0; nt < 4; nt++) {
#pragma unroll
            for (int half = 0; half < 2; half++) {
                int r = warp_m + gid + half * 8;
                float sc = Rinv[r];
                int c = warp_n + nt * 8 + 2 * tig;
                float2 o = make_float2(rnd32(acc[nt][half * 2] * sc),
                                       rnd32(acc[nt][half * 2 + 1] * sc));
                *(float2*)(out + (size_t)(bb * S_ + q0 + r) * H_ + h * 64 + c) = o;
            }
        }
    }
}

// ---------------- host orchestration ----------------
template<int MODE, bool RND>
static void launch_gemm(const float* A, const float* W, const float* bias,
                        const float* res, float* C, int M, int N, int K)
{
    static bool attr_set = false;
    if (!attr_set) {
        cudaFuncSetAttribute(gemm_tc<MODE, RND>,
                             cudaFuncAttributeMaxDynamicSharedMemorySize, GEMM_SMEM_BYTES);
        attr_set = true;
    }
    dim3 grid(N / 128, M / 128);
    gemm_tc<MODE, RND><<<grid, 256, GEMM_SMEM_BYTES>>>(A, W, bias, res, C, M, N, K);
}

extern "C" void kernel_launch(void* const* d_in, const int* in_sizes, int n_in,
                              void* d_out, int out_size)
{
    const float* x     = (const float*)d_in[0];
    const float* w_in  = (const float*)d_in[1];
    const float* w_out = (const float*)d_in[2];
    const float* b_out = (const float*)d_in[3];
    const float* qkv_w = (const float*)d_in[4];
    const float* qkv_b = (const float*)d_in[5];
    const float* out_w = (const float*)d_in[6];
    const float* out_b = (const float*)d_in[7];
    const float* ln1_g = (const float*)d_in[8];
    const float* ln1_b = (const float*)d_in[9];
    const float* ln2_g = (const float*)d_in[10];
    const float* ln2_b = (const float*)d_in[11];
    const float* ff1_w = (const float*)d_in[12];
    const float* ff1_b = (const float*)d_in[13];
    const float* ff2_w = (const float*)d_in[14];
    const float* ff2_b = (const float*)d_in[15];
    const float* lnf_g = (const float*)d_in[16];
    const float* lnf_b = (const float*)d_in[17];
    float* out = (float*)d_out;

    float *h, *z, *qkv, *att, *ffn, *wc, *xr;
    cudaGetSymbolAddress((void**)&h,   g_h);
    cudaGetSymbolAddress((void**)&z,   g_z);
    cudaGetSymbolAddress((void**)&qkv, g_qkv);
    cudaGetSymbolAddress((void**)&att, g_att);
    cudaGetSymbolAddress((void**)&ffn, g_ffn);
    cudaGetSymbolAddress((void**)&wc,  g_wc);
    cudaGetSymbolAddress((void**)&xr,  g_xr);

    const int att_smem_bytes = ATT_SMEM_FLOATS * 4;
    cudaFuncSetAttribute(attn_mma, cudaFuncAttributeMaxDynamicSharedMemorySize,
                         att_smem_bytes);

    // round weights + x to tf32
    prep_cvt<<<(TOT / 4 + 255) / 256, 256>>>(w_in, w_out, qkv_w, out_w, ff1_w, ff2_w,
                                             x, wc, xr);

    // embed: h = 16 * xr @ w_in^T + PE  (fp32 output, feeds LN)
    launch_gemm<3, false>(xr, wc + O_WIN, nullptr, nullptr, h, M_, H_, H_);

    for (int l = 0; l < 3; l++) {
        ln_kernel<<<M_ / 8, 256>>>(h, ln1_g + l * H_, ln1_b + l * H_, z);
        launch_gemm<0, true>(z, wc + O_QKV + (size_t)l * 3 * H_ * H_,
                             qkv_b + l * 3 * H_, nullptr, qkv, M_, 3 * H_, H_);
        attn_mma<<<dim3(S_ / BQ, NHEAD_, B_), 256, att_smem_bytes>>>(qkv, att);
        launch_gemm<2, false>(att, wc + O_OUTW + (size_t)l * H_ * H_,
                              out_b + l * H_, h, h, M_, H_, H_);
        ln_kernel<<<M_ / 8, 256>>>(h, ln2_g + l * H_, ln2_b + l * H_, z);
        launch_gemm<1, true>(z, wc + O_FF1 + (size_t)l * FFN_ * H_,
                             ff1_b + l * FFN_, nullptr, ffn, M_, FFN_, H_);
        launch_gemm<2, false>(ffn, wc + O_FF2 + (size_t)l * H_ * FFN_,
                              ff2_b + l * H_, h, h, M_, H_, FFN_);
    }

    ln_kernel<<<M_ / 8, 256>>>(h, lnf_g, lnf_b, z);
    launch_gemm<0, false>(z, wc + O_WOUT, b_out, nullptr, out, M_, H_, H_);
}